// round 10
// baseline (speedup 1.0000x reference)
#include <cuda_runtime.h>
#include <cuda_fp16.h>
#include <math.h>

#define NB 8192
#define BB 64
#define DD 5
#define NE (NB*DD)      // 40960 neighbor edges
#define NT (NB*BB)      // 524288 (node, batch) rows
#define HC 16

typedef unsigned long long u64;

// ---------------- packed f32x2 helpers (sm_103a) ----------------------------
__device__ __forceinline__ u64 pk2(float lo, float hi) {
    u64 r; asm("mov.b64 %0, {%1, %2};" : "=l"(r) : "f"(lo), "f"(hi)); return r;
}
__device__ __forceinline__ void up2(u64 v, float& lo, float& hi) {
    asm("mov.b64 {%0, %1}, %2;" : "=f"(lo), "=f"(hi) : "l"(v));
}
__device__ __forceinline__ u64 add2(u64 a, u64 b) {
    u64 r; asm("add.rn.f32x2 %0, %1, %2;" : "=l"(r) : "l"(a), "l"(b)); return r;
}
__device__ __forceinline__ u64 mul2(u64 a, u64 b) {
    u64 r; asm("mul.rn.f32x2 %0, %1, %2;" : "=l"(r) : "l"(a), "l"(b)); return r;
}
__device__ __forceinline__ u64 fma2(u64 a, u64 b, u64 c) {
    u64 r; asm("fma.rn.f32x2 %0, %1, %2, %3;" : "=l"(r) : "l"(a), "l"(b), "l"(c)); return r;
}
__device__ __forceinline__ u64 h2_to_f2(unsigned h) {
    float2 f = __half22float2(*reinterpret_cast<__half2*>(&h));
    return pk2(f.x, f.y);
}

// ---------------- device scratch (no runtime allocation allowed) ------------
__device__ __half g_xlA[(size_t)NT * HC];   // 16.8 MB, layout (n,b,hc) fp16
__device__ __half g_xrA[(size_t)NT * HC];
__device__ __half g_xlB[(size_t)NT * HC];
__device__ __half g_xrB[(size_t)NT * HC];
__device__ float  g_h  [(size_t)NT * HC];   // final-layer h only (fp32)
__device__ float  g_poolp[8 * BB * HC];     // pool partials (chunk, b, f)
__device__ int    g_cnt[NB];                // static zero-init; scan re-zeroes
__device__ int    g_off[NB + 1];
__device__ int    g_cur[NB];
__device__ int    g_csr[NE];

// ---------------- fp16 quarter-row <-> fp32 helpers ------------------------
__device__ __forceinline__ uint2 q_f2h(float4 v) {
    __half2 h0 = __floats2half2_rn(v.x, v.y);
    __half2 h1 = __floats2half2_rn(v.z, v.w);
    uint2 u;
    u.x = *reinterpret_cast<unsigned*>(&h0);
    u.y = *reinterpret_cast<unsigned*>(&h1);
    return u;
}

// ---------------- CSR scan (re-zeroes counts for next graph replay) --------
__global__ void scan_kernel() {
    __shared__ int wsum[32];
    int t = threadIdx.x;
    int v[8];
    int s = 0;
#pragma unroll
    for (int i = 0; i < 8; i++) {
        v[i] = g_cnt[t * 8 + i];
        g_cnt[t * 8 + i] = 0;          // reset for next replay
        s += v[i];
    }
    unsigned lane = t & 31, wid = t >> 5;
    int x = s;
#pragma unroll
    for (int o = 1; o < 32; o <<= 1) {
        int y = __shfl_up_sync(0xffffffffu, x, o);
        if (lane >= (unsigned)o) x += y;
    }
    if (lane == 31) wsum[wid] = x;
    __syncthreads();
    if (wid == 0) {
        int w = wsum[lane];
#pragma unroll
        for (int o = 1; o < 32; o <<= 1) {
            int y = __shfl_up_sync(0xffffffffu, w, o);
            if (lane >= (unsigned)o) w += y;
        }
        wsum[lane] = w;
    }
    __syncthreads();
    int excl = x - s + (wid ? wsum[wid - 1] : 0);
    int run = excl;
#pragma unroll
    for (int i = 0; i < 8; i++) {
        g_off[t * 8 + i] = run;
        g_cur[t * 8 + i] = run;
        run += v[i];
    }
    if (t == 1023) g_off[NB] = run;
}

__global__ void fill_kernel(const int* __restrict__ neighbors) {
    int e = blockIdx.x * blockDim.x + threadIdx.x;
    if (e < NE) {
        int dst = neighbors[e];
        int pos = atomicAdd(&g_cur[dst], 1);
        g_csr[pos] = e / DD;   // source node of edge e
    }
}

// ---------------- layer-0 projections (quad-sliced, f32x2, fp16 out) -------
__global__ __launch_bounds__(256)
void proj0_kernel(const float* __restrict__ xin,
                  const float* __restrict__ neighbors_i,
                  const float* __restrict__ Wl, const float* __restrict__ Wr) {
    __shared__ float sWl[256], sWr[256];
    int t = threadIdx.x;
    sWl[t] = Wl[t];
    sWr[t] = Wr[t];

    // fused CSR count
    int e = blockIdx.x * 256 + t;
    if (e < NE) atomicAdd(&g_cnt[((const int*)neighbors_i)[e]], 1);
    __syncthreads();

    int row = blockIdx.x * 64 + (t >> 2);   // row = n*64 + b
    int hq  = t & 3;
    int n = row >> 6, b = row & 63;

    float4 xq = __ldcs((const float4*)(xin + ((size_t)b * NB + n) * HC) + hq);

    u64 ol01 = 0, ol23 = 0, or01 = 0, or23 = 0;
    int qbase = (t & 31) & ~3;
#pragma unroll
    for (int f = 0; f < 16; f++) {
        float src = (f & 3) == 0 ? xq.x : (f & 3) == 1 ? xq.y
                  : (f & 3) == 2 ? xq.z : xq.w;
        float hf = __shfl_sync(0xffffffffu, src, qbase | (f >> 2), 32);
        u64 hp = pk2(hf, hf);
        float4 wl = *(const float4*)&sWl[f * 16 + hq * 4];
        float4 wr = *(const float4*)&sWr[f * 16 + hq * 4];
        ol01 = fma2(hp, pk2(wl.x, wl.y), ol01);
        ol23 = fma2(hp, pk2(wl.z, wl.w), ol23);
        or01 = fma2(hp, pk2(wr.x, wr.y), or01);
        or23 = fma2(hp, pk2(wr.z, wr.w), or23);
    }
    float4 ov, rv;
    up2(ol01, ov.x, ov.y); up2(ol23, ov.z, ov.w);
    up2(or01, rv.x, rv.y); up2(or23, rv.z, rv.w);
    ((uint2*)(g_xlA + (size_t)row * HC))[hq] = q_f2h(ov);
    ((uint2*)(g_xrA + (size_t)row * HC))[hq] = q_f2h(rv);
}

// ---------------- fused GATv2 layer, head-sliced, fp16 buffers, f32x2 ------
// Block = one node n (256 threads = 64 batches x 4 head-quarters).
// Plain-exp softmax via exp2 (log2e folded into attention weights).
// leaky_relu(z, 0.2) computed as 0.6*z + 0.4*|z|.
template <int IN, bool LAST>
__global__ __launch_bounds__(256)
void gat3_kernel(const float* __restrict__ attw,
                 const float* __restrict__ bias,
                 const float* __restrict__ Wln,   // next layer's Wl (null if LAST)
                 const float* __restrict__ Wrn) { // next layer's Wr (null if LAST)
    __shared__ float sWl[256], sWr[256];
    int t = threadIdx.x;
    if (!LAST) { sWl[t] = Wln[t]; sWr[t] = Wrn[t]; __syncthreads(); }

    const __half* __restrict__ xlin  = (IN == 0) ? g_xlA : g_xlB;
    const __half* __restrict__ xrin  = (IN == 0) ? g_xrA : g_xrB;
    __half*       __restrict__ xlout = (IN == 0) ? g_xlB : g_xlA;
    __half*       __restrict__ xrout = (IN == 0) ? g_xrB : g_xrA;

    int n  = blockIdx.x;
    int b  = t >> 2;
    int hq = t & 3;
    size_t idx = (size_t)n * BB + b;

    const float LOG2E = 1.4426950408889634f;
    float4 att4 = __ldg((const float4*)attw + hq);
    u64 aw01 = pk2(att4.x * LOG2E, att4.y * LOG2E);
    u64 aw23 = pk2(att4.z * LOG2E, att4.w * LOG2E);
    const u64 ABSM = 0x7fffffff7fffffffULL;
    u64 c06 = pk2(0.6f, 0.6f), c04 = pk2(0.4f, 0.4f);

    uint2 xru = ((const uint2*)(xrin + idx * HC))[hq];
    u64 xr01 = h2_to_f2(xru.x), xr23 = h2_to_f2(xru.y);

    // ---- self edge --------------------------------------------------------
    float s;
    u64 acc01, acc23;
    {
        uint2 su = ((const uint2*)(xlin + idx * HC))[hq];
        u64 Q01 = h2_to_f2(su.x), Q23 = h2_to_f2(su.y);
        u64 z01 = add2(Q01, xr01), z23 = add2(Q23, xr23);
        u64 lk01 = fma2(z01 & ABSM, c04, mul2(z01, c06));
        u64 lk23 = fma2(z23 & ABSM, c04, mul2(z23, c06));
        u64 l2 = fma2(lk23, aw23, mul2(lk01, aw01));
        float lx, ly; up2(l2, lx, ly);
        float wgt = exp2f(lx + ly);
        s = wgt;
        u64 wp = pk2(wgt, wgt);
        acc01 = mul2(wp, Q01);
        acc23 = mul2(wp, Q23);
    }

    // ---- incoming-edge loop with 2-deep prefetch --------------------------
    int beg = g_off[n], end = g_off[n + 1];
    int boff = b * HC + hq * 4;            // in half units
    uint2 P0 = make_uint2(0u, 0u), P1 = P0;
    if (beg < end)
        P0 = *(const uint2*)(xlin + (size_t)g_csr[beg] * (BB * HC) + boff);
    if (beg + 1 < end)
        P1 = *(const uint2*)(xlin + (size_t)g_csr[beg + 1] * (BB * HC) + boff);
    for (int e = beg; e < end; e++) {
        u64 Q01 = h2_to_f2(P0.x), Q23 = h2_to_f2(P0.y);
        P0 = P1;
        if (e + 2 < end)
            P1 = *(const uint2*)(xlin + (size_t)g_csr[e + 2] * (BB * HC) + boff);
        u64 z01 = add2(Q01, xr01), z23 = add2(Q23, xr23);
        u64 lk01 = fma2(z01 & ABSM, c04, mul2(z01, c06));
        u64 lk23 = fma2(z23 & ABSM, c04, mul2(z23, c06));
        u64 l2 = fma2(lk23, aw23, mul2(lk01, aw01));
        float lx, ly; up2(l2, lx, ly);
        float wgt = exp2f(lx + ly);
        s += wgt;
        u64 wp = pk2(wgt, wgt);
        acc01 = fma2(wp, Q01, acc01);
        acc23 = fma2(wp, Q23, acc23);
    }

    // ---- finalize quarter of the new h row --------------------------------
    float inv = 1.f / (s + 1e-16f);
    float4 bb4 = __ldg((const float4*)bias + hq);
    u64 ip = pk2(inv, inv);
    u64 o01 = fma2(acc01, ip, pk2(bb4.x, bb4.y));
    u64 o23 = fma2(acc23, ip, pk2(bb4.z, bb4.w));
    float4 o4;
    up2(o01, o4.x, o4.y); up2(o23, o4.z, o4.w);

    if (LAST) {
        ((float4*)(g_h + idx * HC))[hq] = o4;
        return;
    }

    // ---- next-layer projections via quad shuffle (f32x2) ------------------
    u64 ol01 = 0, ol23 = 0, or01 = 0, or23 = 0;
    int qbase = (t & 31) & ~3;
#pragma unroll
    for (int f = 0; f < 16; f++) {
        float src = (f & 3) == 0 ? o4.x : (f & 3) == 1 ? o4.y
                  : (f & 3) == 2 ? o4.z : o4.w;
        float hf = __shfl_sync(0xffffffffu, src, qbase | (f >> 2), 32);
        u64 hp = pk2(hf, hf);
        float4 wl = *(const float4*)&sWl[f * 16 + hq * 4];
        float4 wr = *(const float4*)&sWr[f * 16 + hq * 4];
        ol01 = fma2(hp, pk2(wl.x, wl.y), ol01);
        ol23 = fma2(hp, pk2(wl.z, wl.w), ol23);
        or01 = fma2(hp, pk2(wr.x, wr.y), or01);
        or23 = fma2(hp, pk2(wr.z, wr.w), or23);
    }
    float4 ov, rv;
    up2(ol01, ov.x, ov.y); up2(ol23, ov.z, ov.w);
    up2(or01, rv.x, rv.y); up2(or23, rv.z, rv.w);
    ((uint2*)(xlout + idx * HC))[hq] = q_f2h(ov);
    ((uint2*)(xrout + idx * HC))[hq] = q_f2h(rv);
}

// ---------------- mean-pool over nodes (phase 1: partial sums) -------------
__global__ __launch_bounds__(256)
void pool1_kernel() {
    int b = blockIdx.x >> 3;       // 64 batches
    int chunk = blockIdx.x & 7;    // 8 node chunks of 1024
    int t = threadIdx.x;
    int f = t & 15, g = t >> 4;    // 16 groups
    float sum = 0.f;
    int n0 = chunk * 1024 + g;
    for (int k = 0; k < 64; k++) {
        int n = n0 + k * 16;
        sum += g_h[((size_t)n * BB + b) * HC + f];
    }
    __shared__ float red[256];
    red[t] = sum;
    __syncthreads();
    for (int st = 128; st >= 16; st >>= 1) {
        if (t < st) red[t] += red[t + st];
        __syncthreads();
    }
    if (t < 16) g_poolp[chunk * (BB * HC) + b * HC + t] = red[t];
}

// ---------------- agg MLP + edge scorer, one block per batch ---------------
__global__ __launch_bounds__(128)
void pool2_scorer_kernel(const int* __restrict__ agent_nodes,
                         const int* __restrict__ neighbors,
                         const float* __restrict__ Wg1, const float* __restrict__ bg1,
                         const float* __restrict__ Wg2, const float* __restrict__ bg2,
                         const float* __restrict__ We1, const float* __restrict__ be1,
                         const float* __restrict__ We2, const float* __restrict__ be2,
                         const float* __restrict__ We3, const float* __restrict__ be3,
                         float* __restrict__ out) {
    int b = blockIdx.x;
    int t = threadIdx.x;   // 128 threads
    __shared__ float pool[16], g1[32], agg[64];
    if (t < 16) {
        float s = 0.f;
#pragma unroll
        for (int c = 0; c < 8; c++) s += g_poolp[c * (BB * HC) + b * HC + t];
        pool[t] = s * (1.f / (float)NB);
    }
    __syncthreads();
    if (t < 32) {
        float s = bg1[t];
#pragma unroll
        for (int ff = 0; ff < 16; ff++) s = fmaf(pool[ff], Wg1[ff * 32 + t], s);
        g1[t] = tanhf(s);
    }
    __syncthreads();
    if (t < 64) {
        float s = bg2[t];
#pragma unroll
        for (int k = 0; k < 32; k++) s = fmaf(g1[k], Wg2[k * 64 + t], s);
        agg[t] = tanhf(s);
    }
    __syncthreads();

    if (t >= 3 * DD) return;          // 15 scorer items per batch
    int tk = t / DD;
    int d  = t % DD;
    int an = agent_nodes[b];
    int tg = neighbors[an * DD + d];

    float acc1[16];
#pragma unroll
    for (int o = 0; o < 16; o++) acc1[o] = be1[o];

#pragma unroll
    for (int ff = 0; ff < 16; ff++) {                       // source [0,16)
        float val = g_h[((size_t)an * BB + b) * HC + ff];
#pragma unroll
        for (int o = 0; o < 16; o++) acc1[o] = fmaf(val, We1[ff * 16 + o], acc1[o]);
    }
    {                                                       // token one-hot [16,19)
        int i = 16 + tk;
#pragma unroll
        for (int o = 0; o < 16; o++) acc1[o] += We1[i * 16 + o];
    }
#pragma unroll
    for (int ff = 0; ff < 16; ff++) {                       // target [19,35)
        float val = g_h[((size_t)tg * BB + b) * HC + ff];
#pragma unroll
        for (int o = 0; o < 16; o++) acc1[o] = fmaf(val, We1[(19 + ff) * 16 + o], acc1[o]);
    }
#pragma unroll
    for (int k = 0; k < 64; k++) {                          // agg [35,99)
        float val = agg[k];
#pragma unroll
        for (int o = 0; o < 16; o++) acc1[o] = fmaf(val, We1[(35 + k) * 16 + o], acc1[o]);
    }

    float e1[16];
#pragma unroll
    for (int o = 0; o < 16; o++) e1[o] = tanhf(acc1[o]);

    float e2[8];
#pragma unroll
    for (int o2 = 0; o2 < 8; o2++) {
        float s = be2[o2];
#pragma unroll
        for (int o = 0; o < 16; o++) s = fmaf(e1[o], We2[o * 8 + o2], s);
        e2[o2] = tanhf(s);
    }
    float s3 = be3[0];
#pragma unroll
    for (int o2 = 0; o2 < 8; o2++) s3 = fmaf(e2[o2], We3[o2], s3);
    out[b * (3 * DD) + t] = s3;
}

// ---------------- launch ---------------------------------------------------
extern "C" void kernel_launch(void* const* d_in, const int* in_sizes, int n_in,
                              void* d_out, int out_size) {
    const float* x      = (const float*)d_in[0];
    const int*   agent  = (const int*)  d_in[1];
    const int*   nbr    = (const int*)  d_in[2];
    const float* Wl     = (const float*)d_in[3];
    const float* Wr     = (const float*)d_in[4];
    const float* attw   = (const float*)d_in[5];
    const float* bias   = (const float*)d_in[6];
    const float* Wg1    = (const float*)d_in[7];
    const float* bg1    = (const float*)d_in[8];
    const float* Wg2    = (const float*)d_in[9];
    const float* bg2    = (const float*)d_in[10];
    const float* We1    = (const float*)d_in[11];
    const float* be1    = (const float*)d_in[12];
    const float* We2    = (const float*)d_in[13];
    const float* be2    = (const float*)d_in[14];
    const float* We3    = (const float*)d_in[15];
    const float* be3    = (const float*)d_in[16];
    float* out = (float*)d_out;

    // layer-0 projections (with fused CSR degree count)
    proj0_kernel<<<NT / 64, 256>>>(x, (const float*)nbr, Wl, Wr);
    scan_kernel<<<1, 1024>>>();
    fill_kernel<<<(NE + 255) / 256, 256>>>(nbr);

    // 4 fused GATv2 layers (buffers ping-pong A->B->A->B), 1 node/block
    gat3_kernel<0, false><<<NB, 256>>>(attw,      bias,      Wl + 256, Wr + 256);
    gat3_kernel<1, false><<<NB, 256>>>(attw + 16, bias + 16, Wl + 512, Wr + 512);
    gat3_kernel<0, false><<<NB, 256>>>(attw + 32, bias + 32, Wl + 768, Wr + 768);
    gat3_kernel<1, true ><<<NB, 256>>>(attw + 48, bias + 48, nullptr,  nullptr);

    // pooling partials, then agg-MLP + scorer fused (one block per batch)
    pool1_kernel<<<BB * 8, 256>>>();
    pool2_scorer_kernel<<<BB, 128>>>(agent, nbr, Wg1, bg1, Wg2, bg2,
                                     We1, be1, We2, be2, We3, be3, out);
}

// round 12
// speedup vs baseline: 1.2262x; 1.2262x over previous
#include <cuda_runtime.h>
#include <cuda_fp16.h>
#include <math.h>

#define NB 8192
#define BB 64
#define DD 5
#define NE (NB*DD)      // 40960 neighbor edges
#define NT (NB*BB)      // 524288 (node, batch) rows
#define HC 16

// ---------------- device scratch (no runtime allocation allowed) ------------
__device__ __half g_xlA[(size_t)NT * HC];   // 16.8 MB, layout (n,b,hc) fp16
__device__ __half g_xrA[(size_t)NT * HC];
__device__ __half g_xlB[(size_t)NT * HC];
__device__ __half g_xrB[(size_t)NT * HC];
__device__ float  g_h  [(size_t)NT * HC];   // final-layer h only (fp32)
__device__ float  g_poolp[8 * BB * HC];     // pool partials (chunk, b, f)
__device__ int    g_cnt[NB];                // static zero-init; scan re-zeroes
__device__ int    g_off[NB + 1];
__device__ int    g_cur[NB];
__device__ int    g_csr[NE];

// ---------------- fp16 quarter-row <-> fp32 helpers ------------------------
__device__ __forceinline__ float4 q_h2f(uint2 u) {
    float2 f0 = __half22float2(*reinterpret_cast<__half2*>(&u.x));
    float2 f1 = __half22float2(*reinterpret_cast<__half2*>(&u.y));
    return make_float4(f0.x, f0.y, f1.x, f1.y);
}
__device__ __forceinline__ uint2 q_f2h(float4 v) {
    __half2 h0 = __floats2half2_rn(v.x, v.y);
    __half2 h1 = __floats2half2_rn(v.z, v.w);
    uint2 u;
    u.x = *reinterpret_cast<unsigned*>(&h0);
    u.y = *reinterpret_cast<unsigned*>(&h1);
    return u;
}

// ---------------- CSR scan (re-zeroes counts for next graph replay) --------
__global__ void scan_kernel() {
    __shared__ int wsum[32];
    int t = threadIdx.x;
    int v[8];
    int s = 0;
#pragma unroll
    for (int i = 0; i < 8; i++) {
        v[i] = g_cnt[t * 8 + i];
        g_cnt[t * 8 + i] = 0;          // reset for next replay
        s += v[i];
    }
    unsigned lane = t & 31, wid = t >> 5;
    int x = s;
#pragma unroll
    for (int o = 1; o < 32; o <<= 1) {
        int y = __shfl_up_sync(0xffffffffu, x, o);
        if (lane >= (unsigned)o) x += y;
    }
    if (lane == 31) wsum[wid] = x;
    __syncthreads();
    if (wid == 0) {
        int w = wsum[lane];
#pragma unroll
        for (int o = 1; o < 32; o <<= 1) {
            int y = __shfl_up_sync(0xffffffffu, w, o);
            if (lane >= (unsigned)o) w += y;
        }
        wsum[lane] = w;
    }
    __syncthreads();
    int excl = x - s + (wid ? wsum[wid - 1] : 0);
    int run = excl;
#pragma unroll
    for (int i = 0; i < 8; i++) {
        g_off[t * 8 + i] = run;
        g_cur[t * 8 + i] = run;
        run += v[i];
    }
    if (t == 1023) g_off[NB] = run;
}

__global__ void fill_kernel(const int* __restrict__ neighbors) {
    int e = blockIdx.x * blockDim.x + threadIdx.x;
    if (e < NE) {
        int dst = neighbors[e];
        int pos = atomicAdd(&g_cur[dst], 1);
        g_csr[pos] = e / DD;   // source node of edge e
    }
}

// ---------------- layer-0 projections (quad-sliced, coalesced, fp16 out) ---
__global__ __launch_bounds__(256)
void proj0_kernel(const float* __restrict__ xin,
                  const float* __restrict__ neighbors_i,
                  const float* __restrict__ Wl, const float* __restrict__ Wr) {
    __shared__ float sWl[256], sWr[256];
    int t = threadIdx.x;
    sWl[t] = Wl[t];
    sWr[t] = Wr[t];

    // fused CSR count
    int e = blockIdx.x * 256 + t;
    if (e < NE) atomicAdd(&g_cnt[((const int*)neighbors_i)[e]], 1);
    __syncthreads();

    int row = blockIdx.x * 64 + (t >> 2);   // row = n*64 + b
    int hq  = t & 3;
    int n = row >> 6, b = row & 63;

    float4 xq = __ldcs((const float4*)(xin + ((size_t)b * NB + n) * HC) + hq);

    float4 ol  = make_float4(0.f, 0.f, 0.f, 0.f);
    float4 orr = ol;
    int qbase = (t & 31) & ~3;
#pragma unroll
    for (int f = 0; f < 16; f++) {
        float src = (f & 3) == 0 ? xq.x : (f & 3) == 1 ? xq.y
                  : (f & 3) == 2 ? xq.z : xq.w;
        float hf = __shfl_sync(0xffffffffu, src, qbase | (f >> 2), 32);
        float4 wl = *(const float4*)&sWl[f * 16 + hq * 4];
        float4 wr = *(const float4*)&sWr[f * 16 + hq * 4];
        ol.x  = fmaf(hf, wl.x, ol.x);  ol.y  = fmaf(hf, wl.y, ol.y);
        ol.z  = fmaf(hf, wl.z, ol.z);  ol.w  = fmaf(hf, wl.w, ol.w);
        orr.x = fmaf(hf, wr.x, orr.x); orr.y = fmaf(hf, wr.y, orr.y);
        orr.z = fmaf(hf, wr.z, orr.z); orr.w = fmaf(hf, wr.w, orr.w);
    }
    ((uint2*)(g_xlA + (size_t)row * HC))[hq] = q_f2h(ol);
    ((uint2*)(g_xrA + (size_t)row * HC))[hq] = q_f2h(orr);
}

// ---------------- fused GATv2 layer: 2 rows/thread, head-sliced, fp16 ------
// Block = one node n, 128 threads = 32 batch-pairs x 4 head-quarters.
// Thread (b0 = t>>2, hq = t&3) handles batches b0 and b0+32: shares the
// CSR walk and the epilogue weight reads across both rows.
template <int IN, bool LAST>
__global__ __launch_bounds__(128)
void gat4_kernel(const float* __restrict__ attw,
                 const float* __restrict__ bias,
                 const float* __restrict__ Wln,   // next layer's Wl (null if LAST)
                 const float* __restrict__ Wrn) { // next layer's Wr (null if LAST)
    __shared__ float sWl[256], sWr[256];
    int t = threadIdx.x;
    if (!LAST) {
        sWl[t] = Wln[t]; sWl[t + 128] = Wln[t + 128];
        sWr[t] = Wrn[t]; sWr[t + 128] = Wrn[t + 128];
        __syncthreads();
    }

    const __half* __restrict__ xlin  = (IN == 0) ? g_xlA : g_xlB;
    const __half* __restrict__ xrin  = (IN == 0) ? g_xrA : g_xrB;
    __half*       __restrict__ xlout = (IN == 0) ? g_xlB : g_xlA;
    __half*       __restrict__ xrout = (IN == 0) ? g_xrB : g_xrA;

    int n  = blockIdx.x;
    int b0 = t >> 2;           // 0..31
    int hq = t & 3;
    size_t idx0 = (size_t)n * BB + b0;     // row A
    size_t idx1 = idx0 + 32;               // row B (b0+32)

    const float LOG2E = 1.4426950408889634f;
    float4 att4 = __ldg((const float4*)attw + hq);
    att4.x *= LOG2E; att4.y *= LOG2E; att4.z *= LOG2E; att4.w *= LOG2E;

    float4 xrA = q_h2f(((const uint2*)(xrin + idx0 * HC))[hq]);
    float4 xrB = q_h2f(((const uint2*)(xrin + idx1 * HC))[hq]);

    // ---- self edges -------------------------------------------------------
    float sA, sB;
    float4 accA, accB;
    {
        float4 v = q_h2f(((const uint2*)(xlin + idx0 * HC))[hq]);
        float z, l;
        z = v.x + xrA.x; l  = fmaxf(z, 0.2f * z) * att4.x;
        z = v.y + xrA.y; l += fmaxf(z, 0.2f * z) * att4.y;
        z = v.z + xrA.z; l += fmaxf(z, 0.2f * z) * att4.z;
        z = v.w + xrA.w; l += fmaxf(z, 0.2f * z) * att4.w;
        float w = exp2f(l);
        sA = w;
        accA = make_float4(w * v.x, w * v.y, w * v.z, w * v.w);
    }
    {
        float4 v = q_h2f(((const uint2*)(xlin + idx1 * HC))[hq]);
        float z, l;
        z = v.x + xrB.x; l  = fmaxf(z, 0.2f * z) * att4.x;
        z = v.y + xrB.y; l += fmaxf(z, 0.2f * z) * att4.y;
        z = v.z + xrB.z; l += fmaxf(z, 0.2f * z) * att4.z;
        z = v.w + xrB.w; l += fmaxf(z, 0.2f * z) * att4.w;
        float w = exp2f(l);
        sB = w;
        accB = make_float4(w * v.x, w * v.y, w * v.z, w * v.w);
    }

    // ---- incoming-edge loop, both rows, 2-deep prefetch -------------------
    int beg = __ldg(&g_off[n]), end = __ldg(&g_off[n + 1]);
    int offA = b0 * HC + hq * 4;           // half units
    int offB = offA + 32 * HC;
    uint2 PA0 = make_uint2(0u, 0u), PB0 = PA0, PA1 = PA0, PB1 = PA0;
    if (beg < end) {
        const __half* p = xlin + (size_t)__ldg(&g_csr[beg]) * (BB * HC);
        PA0 = *(const uint2*)(p + offA);
        PB0 = *(const uint2*)(p + offB);
    }
    if (beg + 1 < end) {
        const __half* p = xlin + (size_t)__ldg(&g_csr[beg + 1]) * (BB * HC);
        PA1 = *(const uint2*)(p + offA);
        PB1 = *(const uint2*)(p + offB);
    }
    for (int e = beg; e < end; e++) {
        float4 QA = q_h2f(PA0);
        float4 QB = q_h2f(PB0);
        PA0 = PA1; PB0 = PB1;
        if (e + 2 < end) {
            const __half* p = xlin + (size_t)__ldg(&g_csr[e + 2]) * (BB * HC);
            PA1 = *(const uint2*)(p + offA);
            PB1 = *(const uint2*)(p + offB);
        }
        float z, l;
        z = QA.x + xrA.x; l  = fmaxf(z, 0.2f * z) * att4.x;
        z = QA.y + xrA.y; l += fmaxf(z, 0.2f * z) * att4.y;
        z = QA.z + xrA.z; l += fmaxf(z, 0.2f * z) * att4.z;
        z = QA.w + xrA.w; l += fmaxf(z, 0.2f * z) * att4.w;
        float wA = exp2f(l);
        sA += wA;
        accA.x = fmaf(wA, QA.x, accA.x);
        accA.y = fmaf(wA, QA.y, accA.y);
        accA.z = fmaf(wA, QA.z, accA.z);
        accA.w = fmaf(wA, QA.w, accA.w);

        z = QB.x + xrB.x; l  = fmaxf(z, 0.2f * z) * att4.x;
        z = QB.y + xrB.y; l += fmaxf(z, 0.2f * z) * att4.y;
        z = QB.z + xrB.z; l += fmaxf(z, 0.2f * z) * att4.z;
        z = QB.w + xrB.w; l += fmaxf(z, 0.2f * z) * att4.w;
        float wB = exp2f(l);
        sB += wB;
        accB.x = fmaf(wB, QB.x, accB.x);
        accB.y = fmaf(wB, QB.y, accB.y);
        accB.z = fmaf(wB, QB.z, accB.z);
        accB.w = fmaf(wB, QB.w, accB.w);
    }

    // ---- finalize both new h quarters -------------------------------------
    float4 bb4 = __ldg((const float4*)bias + hq);
    float invA = 1.f / (sA + 1e-16f);
    float invB = 1.f / (sB + 1e-16f);
    float4 oA = make_float4(accA.x * invA + bb4.x, accA.y * invA + bb4.y,
                            accA.z * invA + bb4.z, accA.w * invA + bb4.w);
    float4 oB = make_float4(accB.x * invB + bb4.x, accB.y * invB + bb4.y,
                            accB.z * invB + bb4.z, accB.w * invB + bb4.w);

    if (LAST) {
        ((float4*)(g_h + idx0 * HC))[hq] = oA;
        ((float4*)(g_h + idx1 * HC))[hq] = oB;
        return;
    }

    // ---- next-layer projections: quad shuffle, weights shared by 2 rows ---
    float4 olA = make_float4(0.f, 0.f, 0.f, 0.f), orA = olA;
    float4 olB = olA, orB = olA;
    int qbase = (t & 31) & ~3;
#pragma unroll
    for (int f = 0; f < 16; f++) {
        float srcA = (f & 3) == 0 ? oA.x : (f & 3) == 1 ? oA.y
                   : (f & 3) == 2 ? oA.z : oA.w;
        float srcB = (f & 3) == 0 ? oB.x : (f & 3) == 1 ? oB.y
                   : (f & 3) == 2 ? oB.z : oB.w;
        float hfA = __shfl_sync(0xffffffffu, srcA, qbase | (f >> 2), 32);
        float hfB = __shfl_sync(0xffffffffu, srcB, qbase | (f >> 2), 32);
        float4 wl = *(const float4*)&sWl[f * 16 + hq * 4];
        float4 wr = *(const float4*)&sWr[f * 16 + hq * 4];
        olA.x = fmaf(hfA, wl.x, olA.x); olA.y = fmaf(hfA, wl.y, olA.y);
        olA.z = fmaf(hfA, wl.z, olA.z); olA.w = fmaf(hfA, wl.w, olA.w);
        orA.x = fmaf(hfA, wr.x, orA.x); orA.y = fmaf(hfA, wr.y, orA.y);
        orA.z = fmaf(hfA, wr.z, orA.z); orA.w = fmaf(hfA, wr.w, orA.w);
        olB.x = fmaf(hfB, wl.x, olB.x); olB.y = fmaf(hfB, wl.y, olB.y);
        olB.z = fmaf(hfB, wl.z, olB.z); olB.w = fmaf(hfB, wl.w, olB.w);
        orB.x = fmaf(hfB, wr.x, orB.x); orB.y = fmaf(hfB, wr.y, orB.y);
        orB.z = fmaf(hfB, wr.z, orB.z); orB.w = fmaf(hfB, wr.w, orB.w);
    }
    ((uint2*)(xlout + idx0 * HC))[hq] = q_f2h(olA);
    ((uint2*)(xrout + idx0 * HC))[hq] = q_f2h(orA);
    ((uint2*)(xlout + idx1 * HC))[hq] = q_f2h(olB);
    ((uint2*)(xrout + idx1 * HC))[hq] = q_f2h(orB);
}

// ---------------- mean-pool over nodes (phase 1: partial sums) -------------
__global__ __launch_bounds__(256)
void pool1_kernel() {
    int b = blockIdx.x >> 3;       // 64 batches
    int chunk = blockIdx.x & 7;    // 8 node chunks of 1024
    int t = threadIdx.x;
    int f = t & 15, g = t >> 4;    // 16 groups
    float sum = 0.f;
    int n0 = chunk * 1024 + g;
    for (int k = 0; k < 64; k++) {
        int n = n0 + k * 16;
        sum += g_h[((size_t)n * BB + b) * HC + f];
    }
    __shared__ float red[256];
    red[t] = sum;
    __syncthreads();
    for (int st = 128; st >= 16; st >>= 1) {
        if (t < st) red[t] += red[t + st];
        __syncthreads();
    }
    if (t < 16) g_poolp[chunk * (BB * HC) + b * HC + t] = red[t];
}

// ---------------- agg MLP + edge scorer, one block per batch ---------------
__global__ __launch_bounds__(128)
void pool2_scorer_kernel(const int* __restrict__ agent_nodes,
                         const int* __restrict__ neighbors,
                         const float* __restrict__ Wg1, const float* __restrict__ bg1,
                         const float* __restrict__ Wg2, const float* __restrict__ bg2,
                         const float* __restrict__ We1, const float* __restrict__ be1,
                         const float* __restrict__ We2, const float* __restrict__ be2,
                         const float* __restrict__ We3, const float* __restrict__ be3,
                         float* __restrict__ out) {
    int b = blockIdx.x;
    int t = threadIdx.x;   // 128 threads
    __shared__ float pool[16], g1[32], agg[64];
    if (t < 16) {
        float s = 0.f;
#pragma unroll
        for (int c = 0; c < 8; c++) s += g_poolp[c * (BB * HC) + b * HC + t];
        pool[t] = s * (1.f / (float)NB);
    }
    __syncthreads();
    if (t < 32) {
        float s = bg1[t];
#pragma unroll
        for (int ff = 0; ff < 16; ff++) s = fmaf(pool[ff], Wg1[ff * 32 + t], s);
        g1[t] = tanhf(s);
    }
    __syncthreads();
    if (t < 64) {
        float s = bg2[t];
#pragma unroll
        for (int k = 0; k < 32; k++) s = fmaf(g1[k], Wg2[k * 64 + t], s);
        agg[t] = tanhf(s);
    }
    __syncthreads();

    if (t >= 3 * DD) return;          // 15 scorer items per batch
    int tk = t / DD;
    int d  = t % DD;
    int an = agent_nodes[b];
    int tg = neighbors[an * DD + d];

    float acc1[16];
#pragma unroll
    for (int o = 0; o < 16; o++) acc1[o] = be1[o];

#pragma unroll
    for (int ff = 0; ff < 16; ff++) {                       // source [0,16)
        float val = g_h[((size_t)an * BB + b) * HC + ff];
#pragma unroll
        for (int o = 0; o < 16; o++) acc1[o] = fmaf(val, We1[ff * 16 + o], acc1[o]);
    }
    {                                                       // token one-hot [16,19)
        int i = 16 + tk;
#pragma unroll
        for (int o = 0; o < 16; o++) acc1[o] += We1[i * 16 + o];
    }
#pragma unroll
    for (int ff = 0; ff < 16; ff++) {                       // target [19,35)
        float val = g_h[((size_t)tg * BB + b) * HC + ff];
#pragma unroll
        for (int o = 0; o < 16; o++) acc1[o] = fmaf(val, We1[(19 + ff) * 16 + o], acc1[o]);
    }
#pragma unroll
    for (int k = 0; k < 64; k++) {                          // agg [35,99)
        float val = agg[k];
#pragma unroll
        for (int o = 0; o < 16; o++) acc1[o] = fmaf(val, We1[(35 + k) * 16 + o], acc1[o]);
    }

    float e1[16];
#pragma unroll
    for (int o = 0; o < 16; o++) e1[o] = tanhf(acc1[o]);

    float e2[8];
#pragma unroll
    for (int o2 = 0; o2 < 8; o2++) {
        float s = be2[o2];
#pragma unroll
        for (int o = 0; o < 16; o++) s = fmaf(e1[o], We2[o * 8 + o2], s);
        e2[o2] = tanhf(s);
    }
    float s3 = be3[0];
#pragma unroll
    for (int o2 = 0; o2 < 8; o2++) s3 = fmaf(e2[o2], We3[o2], s3);
    out[b * (3 * DD) + t] = s3;
}

// ---------------- launch ---------------------------------------------------
extern "C" void kernel_launch(void* const* d_in, const int* in_sizes, int n_in,
                              void* d_out, int out_size) {
    const float* x      = (const float*)d_in[0];
    const int*   agent  = (const int*)  d_in[1];
    const int*   nbr    = (const int*)  d_in[2];
    const float* Wl     = (const float*)d_in[3];
    const float* Wr     = (const float*)d_in[4];
    const float* attw   = (const float*)d_in[5];
    const float* bias   = (const float*)d_in[6];
    const float* Wg1    = (const float*)d_in[7];
    const float* bg1    = (const float*)d_in[8];
    const float* Wg2    = (const float*)d_in[9];
    const float* bg2    = (const float*)d_in[10];
    const float* We1    = (const float*)d_in[11];
    const float* be1    = (const float*)d_in[12];
    const float* We2    = (const float*)d_in[13];
    const float* be2    = (const float*)d_in[14];
    const float* We3    = (const float*)d_in[15];
    const float* be3    = (const float*)d_in[16];
    float* out = (float*)d_out;

    // layer-0 projections (with fused CSR degree count)
    proj0_kernel<<<NT / 64, 256>>>(x, (const float*)nbr, Wl, Wr);
    scan_kernel<<<1, 1024>>>();
    fill_kernel<<<(NE + 255) / 256, 256>>>(nbr);

    // 4 fused GATv2 layers (buffers ping-pong A->B->A->B), 1 node/block,
    // 2 rows per thread
    gat4_kernel<0, false><<<NB, 128>>>(attw,      bias,      Wl + 256, Wr + 256);
    gat4_kernel<1, false><<<NB, 128>>>(attw + 16, bias + 16, Wl + 512, Wr + 512);
    gat4_kernel<0, false><<<NB, 128>>>(attw + 32, bias + 32, Wl + 768, Wr + 768);
    gat4_kernel<1, true ><<<NB, 128>>>(attw + 48, bias + 48, nullptr,  nullptr);

    // pooling partials, then agg-MLP + scorer fused (one block per batch)
    pool1_kernel<<<BB * 8, 256>>>();
    pool2_scorer_kernel<<<BB, 128>>>(agent, nbr, Wg1, bg1, Wg2, bg2,
                                     We1, be1, We2, be2, We3, be3, out);
}